// round 1
// baseline (speedup 1.0000x reference)
#include <cuda_runtime.h>
#include <math.h>
#include <stdint.h>

// Problem dims
#define kT   512
#define kB   64
#define kH   1024
#define kBH  (kB * kH)           // 65536
#define kTBH (kT * kBH)          // 33554432

#define RNN_NBLK 128             // persistent recurrence grid (<= SM count, deadlock-safe)

// ---------------------------------------------------------------------------
// Scratch (device globals; no allocations allowed)
// ---------------------------------------------------------------------------
__device__ float g_X[kTBH];        // X0 then X1 (precomputed input-side GEMM + biases)
__device__ float g_Hall[kTBH];     // layer-0 hidden states for all t
__device__ float g_hbuf[2][kBH];   // recurrence ping-pong h
__device__ float g_part[8][kBH];   // k-split partial sums
__device__ unsigned g_gen = 0;     // grid barrier generation
__device__ unsigned g_cnt = 0;     // grid barrier arrival count

// ---------------------------------------------------------------------------
// Grid-wide barrier (generation-counting; all RNN_NBLK CTAs are co-resident)
// ---------------------------------------------------------------------------
__device__ __forceinline__ void gridbar()
{
    __threadfence();              // publish this thread's stores to GPU scope
    __syncthreads();
    if (threadIdx.x == 0) {
        volatile unsigned* vg = &g_gen;
        unsigned target = *vg + 1u;           // stable: bumped only by last arriver
        if (atomicAdd(&g_cnt, 1u) == (unsigned)(RNN_NBLK - 1)) {
            g_cnt = 0u;
            __threadfence();
            *vg = target;
        } else {
            while (*vg != target) { __nanosleep(32); }
        }
    }
    __syncthreads();
}

// ---------------------------------------------------------------------------
// SGEMM with fused double-bias: C[M,1024] = A[M,1024] @ W[1024,1024]^T + b1 + b2
// BM=BN=128, BK=8, 256 threads, 8x8 per-thread register tile.
// ---------------------------------------------------------------------------
__global__ void __launch_bounds__(256, 2) sgemm_bias(
    const float* __restrict__ A,
    const float* __restrict__ W,
    const float* __restrict__ b1,
    const float* __restrict__ b2,
    float* __restrict__ C)
{
    __shared__ __align__(16) float As[8][128];
    __shared__ __align__(16) float Ws[8][128];

    const int n0  = blockIdx.x * 128;
    const int m0  = blockIdx.y * 128;
    const int tid = threadIdx.x;
    const int tx  = tid & 15;        // n-group
    const int ty  = tid >> 4;        // m-group
    const int lr  = tid >> 1;        // staging row 0..127
    const int lk  = (tid & 1) << 2;  // staging k offset (0 or 4)

    const float* Ap = A + (size_t)(m0 + lr) * kH + lk;
    const float* Wp = W + (size_t)(n0 + lr) * kH + lk;

    float acc[8][8];
#pragma unroll
    for (int i = 0; i < 8; i++)
#pragma unroll
        for (int j = 0; j < 8; j++) acc[i][j] = 0.f;

    float4 av = *(const float4*)(Ap);
    float4 wv = *(const float4*)(Wp);

    for (int k0 = 0; k0 < kH; k0 += 8) {
        As[lk + 0][lr] = av.x; As[lk + 1][lr] = av.y;
        As[lk + 2][lr] = av.z; As[lk + 3][lr] = av.w;
        Ws[lk + 0][lr] = wv.x; Ws[lk + 1][lr] = wv.y;
        Ws[lk + 2][lr] = wv.z; Ws[lk + 3][lr] = wv.w;
        __syncthreads();

        if (k0 + 8 < kH) {   // prefetch next tile (latency hidden by compute)
            av = *(const float4*)(Ap + k0 + 8);
            wv = *(const float4*)(Wp + k0 + 8);
        }

#pragma unroll
        for (int kk = 0; kk < 8; kk++) {
            float4 a0 = *(const float4*)(&As[kk][ty * 8]);
            float4 a1 = *(const float4*)(&As[kk][ty * 8 + 4]);
            float4 w0 = *(const float4*)(&Ws[kk][tx * 8]);
            float4 w1 = *(const float4*)(&Ws[kk][tx * 8 + 4]);
            float af[8] = {a0.x, a0.y, a0.z, a0.w, a1.x, a1.y, a1.z, a1.w};
            float wf[8] = {w0.x, w0.y, w0.z, w0.w, w1.x, w1.y, w1.z, w1.w};
#pragma unroll
            for (int i = 0; i < 8; i++)
#pragma unroll
                for (int j = 0; j < 8; j++)
                    acc[i][j] = fmaf(af[i], wf[j], acc[i][j]);
        }
        __syncthreads();
    }

    float bias[8];
#pragma unroll
    for (int j = 0; j < 8; j++) {
        int c = n0 + tx * 8 + j;
        bias[j] = b1[c] + b2[c];
    }
#pragma unroll
    for (int i = 0; i < 8; i++) {
        float* Cp = C + (size_t)(m0 + ty * 8 + i) * kH + n0 + tx * 8;
#pragma unroll
        for (int j = 0; j < 8; j++) Cp[j] = acc[i][j] + bias[j];
    }
}

// ---------------------------------------------------------------------------
// Persistent recurrence: for t in 0..T-1: h = tanh(X[t] + h @ Whh^T)
// Grid: 128 CTAs = 16 n-tiles (64 cols) x 8 k-chunks (128 k).
// W slice staged to SMEM ONCE (step-invariant). h re-staged per step (__ldcg:
// inter-SM data must bypass L1 within a single launch).
// Phase A: partial GEMM -> g_part.  barrier.
// Phase B: reduce 8 partials + X, tanh, write h_new / Yall.  barrier.
// ---------------------------------------------------------------------------
__global__ void __launch_bounds__(256) rnn_layer(
    const float* __restrict__ Whh,    // [1024,1024]
    const float* __restrict__ hinit,  // [64,1024]
    float* __restrict__ Yall,         // [T,64,1024]
    float* __restrict__ hfinal)       // [64,1024]
{
    extern __shared__ float smem[];
    float (*hs)[65] = (float(*)[65])smem;                 // [128][65]  h, k-major
    float (*ws)[65] = (float(*)[65])(smem + 128 * 65);    // [128][65]  W, k-major

    const int tid = threadIdx.x;
    const int cta = blockIdx.x;
    const int kc  = cta & 7;         // k-chunk 0..7
    const int nt  = cta >> 3;        // n-tile  0..15
    const int k0  = kc * 128;
    const int n0  = nt * 64;
    const int tx  = tid & 15;        // n sub-group (4 cols)
    const int ty  = tid >> 4;        // b sub-group (4 rows)

    // Stage the step-invariant W slice: ws[k'][n'] = Whh[n0+n'][k0+k']
#pragma unroll
    for (int r = 0; r < 8; r++) {
        int i4  = tid + r * 256;          // 0..2047 float4s (64 rows x 32 f4/row)
        int row = i4 >> 5;                // n' 0..63
        int kq  = (i4 & 31) << 2;         // k' base
        float4 v = *(const float4*)(Whh + (size_t)(n0 + row) * kH + k0 + kq);
        ws[kq + 0][row] = v.x; ws[kq + 1][row] = v.y;
        ws[kq + 2][row] = v.z; ws[kq + 3][row] = v.w;
    }

    const int ob0 = cta * 512 + tid;      // phase-B output indices (2 per thread)
    const int ob1 = ob0 + 256;

    for (int t = 0; t < kT; t++) {
        const float* hsrc = (t == 0) ? hinit : g_hbuf[t & 1];

        // Stage h tile: hs[k'][b] = hsrc[b][k0+k']
#pragma unroll
        for (int r = 0; r < 8; r++) {
            int i4  = tid + r * 256;
            int row = i4 >> 5;            // b 0..63
            int kq  = (i4 & 31) << 2;
            float4 v = __ldcg((const float4*)(hsrc + (size_t)row * kH + k0 + kq));
            hs[kq + 0][row] = v.x; hs[kq + 1][row] = v.y;
            hs[kq + 2][row] = v.z; hs[kq + 3][row] = v.w;
        }
        __syncthreads();

        // Phase A: 64x64 tile over k-chunk of 128; 4x4 per thread
        float acc[4][4];
#pragma unroll
        for (int i = 0; i < 4; i++)
#pragma unroll
            for (int j = 0; j < 4; j++) acc[i][j] = 0.f;

#pragma unroll 8
        for (int kk = 0; kk < 128; kk++) {
            float af[4], wf[4];
#pragma unroll
            for (int i = 0; i < 4; i++) af[i] = hs[kk][ty * 4 + i];
#pragma unroll
            for (int j = 0; j < 4; j++) wf[j] = ws[kk][tx * 4 + j];
#pragma unroll
            for (int i = 0; i < 4; i++)
#pragma unroll
                for (int j = 0; j < 4; j++)
                    acc[i][j] = fmaf(af[i], wf[j], acc[i][j]);
        }

#pragma unroll
        for (int i = 0; i < 4; i++) {
            float4 v = make_float4(acc[i][0], acc[i][1], acc[i][2], acc[i][3]);
            *(float4*)(&g_part[kc][(size_t)(ty * 4 + i) * kH + n0 + tx * 4]) = v;
        }

        gridbar();

        // Phase B: reduce partials + X, tanh, publish h
        {
            float s0 = g_X[(size_t)t * kBH + ob0];
            float s1 = g_X[(size_t)t * kBH + ob1];
#pragma unroll
            for (int j = 0; j < 8; j++) {
                s0 += __ldcg(&g_part[j][ob0]);
                s1 += __ldcg(&g_part[j][ob1]);
            }
            float h0v = tanhf(s0);
            float h1v = tanhf(s1);
            float* hnext = g_hbuf[(t + 1) & 1];
            hnext[ob0] = h0v;
            hnext[ob1] = h1v;
            Yall[(size_t)t * kBH + ob0] = h0v;
            Yall[(size_t)t * kBH + ob1] = h1v;
            if (t == kT - 1) {
                hfinal[ob0] = h0v;
                hfinal[ob1] = h1v;
            }
        }

        gridbar();
    }
}

// ---------------------------------------------------------------------------
// Launch
// ---------------------------------------------------------------------------
extern "C" void kernel_launch(void* const* d_in, const int* in_sizes, int n_in,
                              void* d_out, int out_size)
{
    const float* input = (const float*)d_in[0];
    const float* h_0   = (const float*)d_in[1];
    const float* W_ih0 = (const float*)d_in[2];
    const float* b_ih0 = (const float*)d_in[3];
    const float* W_hh0 = (const float*)d_in[4];
    const float* b_hh0 = (const float*)d_in[5];
    const float* W_ih1 = (const float*)d_in[6];
    const float* b_ih1 = (const float*)d_in[7];
    const float* W_hh1 = (const float*)d_in[8];
    const float* b_hh1 = (const float*)d_in[9];
    float* out = (float*)d_out;

    float* gX = nullptr;
    float* gHall = nullptr;
    cudaGetSymbolAddress((void**)&gX, g_X);
    cudaGetSymbolAddress((void**)&gHall, g_Hall);

    const size_t rnn_smem = 2 * 128 * 65 * sizeof(float);   // 66,560 B
    cudaFuncSetAttribute(rnn_layer, cudaFuncAttributeMaxDynamicSharedMemorySize,
                         (int)rnn_smem);

    dim3 ggrid(kH / 128, (kT * kB) / 128);   // (8, 256)

    // Phase 1: X0 = input @ W_ih0^T + b_ih0 + b_hh0
    sgemm_bias<<<ggrid, 256>>>(input, W_ih0, b_ih0, b_hh0, gX);

    // Phase 2: layer-0 recurrence -> g_Hall, final h0 -> out[T*B*H ..]
    rnn_layer<<<RNN_NBLK, 256, rnn_smem>>>(W_hh0, h_0, gHall, out + (size_t)kTBH);

    // Phase 3: X1 = Hall @ W_ih1^T + b_ih1 + b_hh1
    sgemm_bias<<<ggrid, 256>>>(gHall, W_ih1, b_ih1, b_hh1, gX);

    // Phase 4: layer-1 recurrence -> outputs (d_out), final h1 -> out[T*B*H + B*H ..]
    rnn_layer<<<RNN_NBLK, 256, rnn_smem>>>(W_hh1, h_0 + kBH, out,
                                           out + (size_t)kTBH + kBH);
}

// round 2
// speedup vs baseline: 1.0100x; 1.0100x over previous
#include <cuda_runtime.h>
#include <math.h>
#include <stdint.h>

// Problem dims
#define kT   512
#define kB   64
#define kH   1024
#define kBH  (kB * kH)           // 65536
#define kTBH (kT * kBH)          // 33554432

#define RNN_NBLK 128             // persistent recurrence grid (<= SM count, deadlock-safe)

// ---------------------------------------------------------------------------
// Scratch (device globals; no allocations allowed)
// ---------------------------------------------------------------------------
__device__ float g_X[kTBH];        // X0 then X1 (precomputed input-side GEMM + biases)
__device__ float g_Hall[kTBH];     // layer-0 hidden states for all t
__device__ float g_hbuf[2][kBH];   // recurrence ping-pong h
__device__ float g_part[8][kBH];   // k-split partial sums
__device__ unsigned g_gen = 0;     // grid barrier generation
__device__ unsigned g_cnt = 0;     // grid barrier arrival count

// ---------------------------------------------------------------------------
// Grid-wide barrier (generation-counting; all RNN_NBLK CTAs are co-resident)
// ---------------------------------------------------------------------------
__device__ __forceinline__ void gridbar()
{
    __threadfence();              // publish this thread's stores to GPU scope
    __syncthreads();
    if (threadIdx.x == 0) {
        volatile unsigned* vg = &g_gen;
        unsigned target = *vg + 1u;           // stable: bumped only by last arriver
        if (atomicAdd(&g_cnt, 1u) == (unsigned)(RNN_NBLK - 1)) {
            g_cnt = 0u;
            __threadfence();
            *vg = target;
        } else {
            while (*vg != target) { __nanosleep(32); }
        }
    }
    __syncthreads();
}

// ---------------------------------------------------------------------------
// SGEMM with fused double-bias: C[M,1024] = A[M,1024] @ W[1024,1024]^T + b1 + b2
// BM=BN=128, BK=8, 256 threads, 8x8 per-thread register tile.
// ---------------------------------------------------------------------------
__global__ void __launch_bounds__(256, 2) sgemm_bias(
    const float* __restrict__ A,
    const float* __restrict__ W,
    const float* __restrict__ b1,
    const float* __restrict__ b2,
    float* __restrict__ C)
{
    __shared__ __align__(16) float As[8][128];
    __shared__ __align__(16) float Ws[8][128];

    const int n0  = blockIdx.x * 128;
    const int m0  = blockIdx.y * 128;
    const int tid = threadIdx.x;
    const int tx  = tid & 15;        // n-group
    const int ty  = tid >> 4;        // m-group
    const int lr  = tid >> 1;        // staging row 0..127
    const int lk  = (tid & 1) << 2;  // staging k offset (0 or 4)

    const float* Ap = A + (size_t)(m0 + lr) * kH + lk;
    const float* Wp = W + (size_t)(n0 + lr) * kH + lk;

    float acc[8][8];
#pragma unroll
    for (int i = 0; i < 8; i++)
#pragma unroll
        for (int j = 0; j < 8; j++) acc[i][j] = 0.f;

    float4 av = *(const float4*)(Ap);
    float4 wv = *(const float4*)(Wp);

    for (int k0 = 0; k0 < kH; k0 += 8) {
        As[lk + 0][lr] = av.x; As[lk + 1][lr] = av.y;
        As[lk + 2][lr] = av.z; As[lk + 3][lr] = av.w;
        Ws[lk + 0][lr] = wv.x; Ws[lk + 1][lr] = wv.y;
        Ws[lk + 2][lr] = wv.z; Ws[lk + 3][lr] = wv.w;
        __syncthreads();

        if (k0 + 8 < kH) {   // prefetch next tile (latency hidden by compute)
            av = *(const float4*)(Ap + k0 + 8);
            wv = *(const float4*)(Wp + k0 + 8);
        }

#pragma unroll
        for (int kk = 0; kk < 8; kk++) {
            float4 a0 = *(const float4*)(&As[kk][ty * 8]);
            float4 a1 = *(const float4*)(&As[kk][ty * 8 + 4]);
            float4 w0 = *(const float4*)(&Ws[kk][tx * 8]);
            float4 w1 = *(const float4*)(&Ws[kk][tx * 8 + 4]);
            float af[8] = {a0.x, a0.y, a0.z, a0.w, a1.x, a1.y, a1.z, a1.w};
            float wf[8] = {w0.x, w0.y, w0.z, w0.w, w1.x, w1.y, w1.z, w1.w};
#pragma unroll
            for (int i = 0; i < 8; i++)
#pragma unroll
                for (int j = 0; j < 8; j++)
                    acc[i][j] = fmaf(af[i], wf[j], acc[i][j]);
        }
        __syncthreads();
    }

    float bias[8];
#pragma unroll
    for (int j = 0; j < 8; j++) {
        int c = n0 + tx * 8 + j;
        bias[j] = b1[c] + b2[c];
    }
#pragma unroll
    for (int i = 0; i < 8; i++) {
        float* Cp = C + (size_t)(m0 + ty * 8 + i) * kH + n0 + tx * 8;
#pragma unroll
        for (int j = 0; j < 8; j++) Cp[j] = acc[i][j] + bias[j];
    }
}

// ---------------------------------------------------------------------------
// Persistent recurrence: for t in 0..T-1: h = tanh(X[t] + h @ Whh^T)
// Grid: 128 CTAs = 16 n-tiles (64 cols) x 8 k-chunks (128 k).
// W slice staged to SMEM ONCE (step-invariant). h re-staged per step (__ldcg:
// inter-SM data must bypass L1 within a single launch).
// Phase A: partial GEMM -> g_part.  barrier.
// Phase B: reduce 8 partials + X, tanh, write h_new / Yall.  barrier.
// ---------------------------------------------------------------------------
__global__ void __launch_bounds__(256) rnn_layer(
    const float* __restrict__ Whh,    // [1024,1024]
    const float* __restrict__ hinit,  // [64,1024]
    float* __restrict__ Yall,         // [T,64,1024]
    float* __restrict__ hfinal)       // [64,1024]
{
    extern __shared__ float smem[];
    float (*hs)[65] = (float(*)[65])smem;                 // [128][65]  h, k-major
    float (*ws)[65] = (float(*)[65])(smem + 128 * 65);    // [128][65]  W, k-major

    const int tid = threadIdx.x;
    const int cta = blockIdx.x;
    const int kc  = cta & 7;         // k-chunk 0..7
    const int nt  = cta >> 3;        // n-tile  0..15
    const int k0  = kc * 128;
    const int n0  = nt * 64;
    const int tx  = tid & 15;        // n sub-group (4 cols)
    const int ty  = tid >> 4;        // b sub-group (4 rows)

    // Stage the step-invariant W slice: ws[k'][n'] = Whh[n0+n'][k0+k']
#pragma unroll
    for (int r = 0; r < 8; r++) {
        int i4  = tid + r * 256;          // 0..2047 float4s (64 rows x 32 f4/row)
        int row = i4 >> 5;                // n' 0..63
        int kq  = (i4 & 31) << 2;         // k' base
        float4 v = *(const float4*)(Whh + (size_t)(n0 + row) * kH + k0 + kq);
        ws[kq + 0][row] = v.x; ws[kq + 1][row] = v.y;
        ws[kq + 2][row] = v.z; ws[kq + 3][row] = v.w;
    }

    const int ob0 = cta * 512 + tid;      // phase-B output indices (2 per thread)
    const int ob1 = ob0 + 256;

    for (int t = 0; t < kT; t++) {
        const float* hsrc = (t == 0) ? hinit : g_hbuf[t & 1];

        // Stage h tile: hs[k'][b] = hsrc[b][k0+k']
#pragma unroll
        for (int r = 0; r < 8; r++) {
            int i4  = tid + r * 256;
            int row = i4 >> 5;            // b 0..63
            int kq  = (i4 & 31) << 2;
            float4 v = __ldcg((const float4*)(hsrc + (size_t)row * kH + k0 + kq));
            hs[kq + 0][row] = v.x; hs[kq + 1][row] = v.y;
            hs[kq + 2][row] = v.z; hs[kq + 3][row] = v.w;
        }
        __syncthreads();

        // Phase A: 64x64 tile over k-chunk of 128; 4x4 per thread
        float acc[4][4];
#pragma unroll
        for (int i = 0; i < 4; i++)
#pragma unroll
            for (int j = 0; j < 4; j++) acc[i][j] = 0.f;

#pragma unroll 8
        for (int kk = 0; kk < 128; kk++) {
            float af[4], wf[4];
#pragma unroll
            for (int i = 0; i < 4; i++) af[i] = hs[kk][ty * 4 + i];
#pragma unroll
            for (int j = 0; j < 4; j++) wf[j] = ws[kk][tx * 4 + j];
#pragma unroll
            for (int i = 0; i < 4; i++)
#pragma unroll
                for (int j = 0; j < 4; j++)
                    acc[i][j] = fmaf(af[i], wf[j], acc[i][j]);
        }

#pragma unroll
        for (int i = 0; i < 4; i++) {
            float4 v = make_float4(acc[i][0], acc[i][1], acc[i][2], acc[i][3]);
            *(float4*)(&g_part[kc][(size_t)(ty * 4 + i) * kH + n0 + tx * 4]) = v;
        }

        gridbar();

        // Phase B: reduce partials + X, tanh, publish h
        {
            float s0 = g_X[(size_t)t * kBH + ob0];
            float s1 = g_X[(size_t)t * kBH + ob1];
#pragma unroll
            for (int j = 0; j < 8; j++) {
                s0 += __ldcg(&g_part[j][ob0]);
                s1 += __ldcg(&g_part[j][ob1]);
            }
            float h0v = tanhf(s0);
            float h1v = tanhf(s1);
            float* hnext = g_hbuf[(t + 1) & 1];
            hnext[ob0] = h0v;
            hnext[ob1] = h1v;
            Yall[(size_t)t * kBH + ob0] = h0v;
            Yall[(size_t)t * kBH + ob1] = h1v;
            if (t == kT - 1) {
                hfinal[ob0] = h0v;
                hfinal[ob1] = h1v;
            }
        }

        gridbar();
    }
}

// ---------------------------------------------------------------------------
// Launch
// ---------------------------------------------------------------------------
extern "C" void kernel_launch(void* const* d_in, const int* in_sizes, int n_in,
                              void* d_out, int out_size)
{
    const float* input = (const float*)d_in[0];
    const float* h_0   = (const float*)d_in[1];
    const float* W_ih0 = (const float*)d_in[2];
    const float* b_ih0 = (const float*)d_in[3];
    const float* W_hh0 = (const float*)d_in[4];
    const float* b_hh0 = (const float*)d_in[5];
    const float* W_ih1 = (const float*)d_in[6];
    const float* b_ih1 = (const float*)d_in[7];
    const float* W_hh1 = (const float*)d_in[8];
    const float* b_hh1 = (const float*)d_in[9];
    float* out = (float*)d_out;

    float* gX = nullptr;
    float* gHall = nullptr;
    cudaGetSymbolAddress((void**)&gX, g_X);
    cudaGetSymbolAddress((void**)&gHall, g_Hall);

    const size_t rnn_smem = 2 * 128 * 65 * sizeof(float);   // 66,560 B
    cudaFuncSetAttribute(rnn_layer, cudaFuncAttributeMaxDynamicSharedMemorySize,
                         (int)rnn_smem);

    dim3 ggrid(kH / 128, (kT * kB) / 128);   // (8, 256)

    // Phase 1: X0 = input @ W_ih0^T + b_ih0 + b_hh0
    sgemm_bias<<<ggrid, 256>>>(input, W_ih0, b_ih0, b_hh0, gX);

    // Phase 2: layer-0 recurrence -> g_Hall, final h0 -> out[T*B*H ..]
    rnn_layer<<<RNN_NBLK, 256, rnn_smem>>>(W_hh0, h_0, gHall, out + (size_t)kTBH);

    // Phase 3: X1 = Hall @ W_ih1^T + b_ih1 + b_hh1
    sgemm_bias<<<ggrid, 256>>>(gHall, W_ih1, b_ih1, b_hh1, gX);

    // Phase 4: layer-1 recurrence -> outputs (d_out), final h1 -> out[T*B*H + B*H ..]
    rnn_layer<<<RNN_NBLK, 256, rnn_smem>>>(W_hh1, h_0 + kBH, out,
                                           out + (size_t)kTBH + kBH);
}

// round 4
// speedup vs baseline: 1.6467x; 1.6304x over previous
#include <cuda_runtime.h>
#include <cuda_bf16.h>
#include <math.h>
#include <stdint.h>

#define kT   512
#define kB   64
#define kH   1024
#define kBH  65536
#define kTB  32768
#define kTBH 33554432
#define RNN_NBLK 128

typedef __nv_bfloat16 bf16;

// ---------------------------------------------------------------------------
// Scratch (device globals; allocations forbidden)
// ---------------------------------------------------------------------------
struct __align__(16) Scratch {
    float X[kTBH];                        // input-side GEMM result (reused per layer)
    bf16  Ahi[kTBH], Alo[kTBH];           // split input
    bf16  Yhi[kTBH], Ylo[kTBH];           // split layer-0 hidden history
    bf16  Whi[4][kH * kH];                // split weights: ih0, hh0, ih1, hh1
    bf16  Wlo[4][kH * kH];
    float bias[2][kH];
    bf16  hinhi[2 * kBH], hinlo[2 * kBH]; // split initial h
    bf16  h1hi[kBH], h1lo[kBH];           // layer-1 running h (stride-0 ring)
    float part[8 * (size_t)kBH];          // k-split partials [kc][b][hidden]
};
__device__ Scratch g_s;
__device__ unsigned g_gen = 0, g_cnt = 0;

// ---------------------------------------------------------------------------
// Warp MMA primitives (baseline ISA: sm_80+ HMMA + ldmatrix — no 'a' features)
// ---------------------------------------------------------------------------
__device__ __forceinline__ uint32_t smem_u32(const void* p) {
    uint32_t r;
    asm("{ .reg .u64 t; cvta.to.shared.u64 t, %1; cvt.u32.u64 %0, t; }" : "=r"(r) : "l"(p));
    return r;
}

#define LDSM4(r, addr)                                                        \
    asm volatile("ldmatrix.sync.aligned.m8n8.x4.shared.b16 {%0,%1,%2,%3}, [%4];" \
        : "=r"((r)[0]), "=r"((r)[1]), "=r"((r)[2]), "=r"((r)[3]) : "r"(addr))

// D(16x8) += A(16x16,row) * B(16x8,col);  A,B bf16, D fp32
#define HMMA(d, a, b)                                                         \
    asm volatile("mma.sync.aligned.m16n8k16.row.col.f32.bf16.bf16.f32 "       \
        "{%0,%1,%2,%3}, {%4,%5,%6,%7}, {%8,%9}, {%0,%1,%2,%3};"               \
        : "+f"((d)[0]), "+f"((d)[1]), "+f"((d)[2]), "+f"((d)[3])              \
        : "r"((a)[0]), "r"((a)[1]), "r"((a)[2]), "r"((a)[3]),                 \
          "r"((b)[0]), "r"((b)[1]))

// ---------------------------------------------------------------------------
// Grid-wide barrier (generation counting; RNN_NBLK co-resident CTAs)
// ---------------------------------------------------------------------------
__device__ __forceinline__ void gridbar() {
    __threadfence();
    __syncthreads();
    if (threadIdx.x == 0) {
        volatile unsigned* vg = &g_gen;
        unsigned target = *vg + 1u;
        if (atomicAdd(&g_cnt, 1u) == (unsigned)(RNN_NBLK - 1)) {
            g_cnt = 0u;
            __threadfence();
            *vg = target;
        } else {
            while (*vg != target) { __nanosleep(20); }
        }
    }
    __syncthreads();
}

// ---------------------------------------------------------------------------
// fp32 -> bf16 hi/lo split
// ---------------------------------------------------------------------------
__global__ void split_pair(const float* __restrict__ s, bf16* __restrict__ hi,
                           bf16* __restrict__ lo, int n4) {
    int stride = gridDim.x * blockDim.x;
    for (int i = blockIdx.x * blockDim.x + threadIdx.x; i < n4; i += stride) {
        float4 v = ((const float4*)s)[i];
        bf16 h0 = __float2bfloat16(v.x), h1 = __float2bfloat16(v.y);
        bf16 h2 = __float2bfloat16(v.z), h3 = __float2bfloat16(v.w);
        ((__nv_bfloat162*)hi)[i * 2 + 0] = __halves2bfloat162(h0, h1);
        ((__nv_bfloat162*)hi)[i * 2 + 1] = __halves2bfloat162(h2, h3);
        ((__nv_bfloat162*)lo)[i * 2 + 0] = __halves2bfloat162(
            __float2bfloat16(v.x - __bfloat162float(h0)),
            __float2bfloat16(v.y - __bfloat162float(h1)));
        ((__nv_bfloat162*)lo)[i * 2 + 1] = __halves2bfloat162(
            __float2bfloat16(v.z - __bfloat162float(h2)),
            __float2bfloat16(v.w - __bfloat162float(h3)));
    }
}

__global__ void bias2(const float* a, const float* b, const float* c,
                      const float* d, float* o0, float* o1) {
    int i = blockIdx.x * 256 + threadIdx.x;
    if (i < kH) { o0[i] = a[i] + b[i]; o1[i] = c[i] + d[i]; }
}

// ---------------------------------------------------------------------------
// Big HMMA GEMM: C[32768,1024] = (Ahi+Alo) @ (Whi+Wlo)^T + bias   (bf16x3)
// 128x128 tile per CTA; 8 warps, 32m x 64n warp tiles; K chunks of 64.
// A rows (seq) = MMA-A (row-major, k contig); W rows = MMA-B "col" (k contig).
// ---------------------------------------------------------------------------
__global__ void __launch_bounds__(256) gemm_mma(
    const bf16* __restrict__ Ahi, const bf16* __restrict__ Alo,
    const bf16* __restrict__ Whi, const bf16* __restrict__ Wlo,
    const float* __restrict__ bias, float* __restrict__ C)
{
    extern __shared__ char sm[];
    enum { RS = 144, BUF = 128 * 144 };       // [128 rows][64+8 pad bf16]
    char* pAh = sm;            char* pAl = sm + BUF;
    char* pWh = sm + 2 * BUF;  char* pWl = sm + 3 * BUF;

    const int tid = threadIdx.x, lane = tid & 31, wid = tid >> 5;
    const int n0 = blockIdx.x * 128, m0 = blockIdx.y * 128;
    const int wm = (wid >> 1) * 32, wn = (wid & 1) * 64;

    const uint32_t aOffH = smem_u32(pAh) + (wm + (lane & 15)) * RS + (lane >> 4) * 16;
    const uint32_t aOffL = smem_u32(pAl) + (wm + (lane & 15)) * RS + (lane >> 4) * 16;
    const int brow = wn + (lane & 7) + ((lane >> 4) & 1) * 8;
    const uint32_t bOffH = smem_u32(pWh) + brow * RS + ((lane >> 3) & 1) * 16;
    const uint32_t bOffL = smem_u32(pWl) + brow * RS + ((lane >> 3) & 1) * 16;

    float acc[2][8][4];
#pragma unroll
    for (int a = 0; a < 2; a++)
#pragma unroll
        for (int b = 0; b < 8; b++)
#pragma unroll
            for (int c = 0; c < 4; c++) acc[a][b][c] = 0.f;

    for (int k0 = 0; k0 < kH; k0 += 64) {
        __syncthreads();
        // stage 4 buffers of [128][64] bf16 (8 uint4/row)
#pragma unroll
        for (int i = 0; i < 4; i++) {
            int q = tid + i * 256;               // 0..1023
            int row = q >> 3, c16 = q & 7;
            size_t ao = (size_t)(m0 + row) * kH + k0 + c16 * 8;
            size_t wo = (size_t)(n0 + row) * kH + k0 + c16 * 8;
            *(uint4*)(pAh + row * RS + c16 * 16) = *(const uint4*)(Ahi + ao);
            *(uint4*)(pAl + row * RS + c16 * 16) = *(const uint4*)(Alo + ao);
            *(uint4*)(pWh + row * RS + c16 * 16) = *(const uint4*)(Whi + wo);
            *(uint4*)(pWl + row * RS + c16 * 16) = *(const uint4*)(Wlo + wo);
        }
        __syncthreads();

#pragma unroll
        for (int kk = 0; kk < 4; kk++) {
            uint32_t ah0[4], ah1[4], al0[4], al1[4];
            LDSM4(ah0, aOffH + kk * 32);
            LDSM4(ah1, aOffH + 16 * RS + kk * 32);
            LDSM4(al0, aOffL + kk * 32);
            LDSM4(al1, aOffL + 16 * RS + kk * 32);
#pragma unroll
            for (int np = 0; np < 4; np++) {     // each LDSM4 covers 2 n8-tiles
                uint32_t bh[4], bl[4];
                LDSM4(bh, bOffH + np * 16 * RS + kk * 32);
                LDSM4(bl, bOffL + np * 16 * RS + kk * 32);
                HMMA(acc[0][np*2+0], ah0, bh+0); HMMA(acc[0][np*2+1], ah0, bh+2);
                HMMA(acc[1][np*2+0], ah1, bh+0); HMMA(acc[1][np*2+1], ah1, bh+2);
                HMMA(acc[0][np*2+0], ah0, bl+0); HMMA(acc[0][np*2+1], ah0, bl+2);
                HMMA(acc[1][np*2+0], ah1, bl+0); HMMA(acc[1][np*2+1], ah1, bl+2);
                HMMA(acc[0][np*2+0], al0, bh+0); HMMA(acc[0][np*2+1], al0, bh+2);
                HMMA(acc[1][np*2+0], al1, bh+0); HMMA(acc[1][np*2+1], al1, bh+2);
            }
        }
    }

    const int g = lane >> 2, tg2 = (lane & 3) * 2;
#pragma unroll
    for (int mf = 0; mf < 2; mf++)
#pragma unroll
        for (int nt = 0; nt < 8; nt++) {
            int m = m0 + wm + mf * 16 + g;
            int n = n0 + wn + nt * 8 + tg2;
            float b0 = bias[n], b1 = bias[n + 1];
            *(float2*)(C + (size_t)m * kH + n) =
                make_float2(acc[mf][nt][0] + b0, acc[mf][nt][1] + b1);
            *(float2*)(C + (size_t)(m + 8) * kH + n) =
                make_float2(acc[mf][nt][2] + b0, acc[mf][nt][3] + b1);
        }
}

// ---------------------------------------------------------------------------
// Persistent HMMA recurrence: for t: h = tanh(X[t] + h @ Whh^T)
// 128 CTAs = 16 hidden-tiles(64) x 8 k-chunks(128). W slice staged once.
// D = [batch 64][hidden 64]: A = h (b x k), B = W rows ("col"). bf16x3.
// Phase A: partial -> part[kc].  gridbar.  Phase B: reduce+tanh+publish. gridbar.
// ---------------------------------------------------------------------------
__global__ void __launch_bounds__(256) rnn_mma(
    const bf16* __restrict__ Whi, const bf16* __restrict__ Wlo,
    const bf16* __restrict__ initHi, const bf16* __restrict__ initLo,
    bf16* __restrict__ Yhi, bf16* __restrict__ Ylo, int ystride,
    const float* __restrict__ X, float* __restrict__ Yfp,
    float* __restrict__ hfinal)
{
    extern __shared__ char sm[];
    enum { RS = 272, BUF = 64 * 272 };        // [64 rows][128+8 pad bf16]
    char* pWh = sm;            char* pWl = sm + BUF;
    char* pHh = sm + 2 * BUF;  char* pHl = sm + 3 * BUF;

    const int tid = threadIdx.x, lane = tid & 31, wid = tid >> 5;
    const int cta = blockIdx.x, mt = cta >> 3, kc = cta & 7;
    const int h0c = mt * 64;                  // hidden-column base
    const int k0 = kc * 128;
    const int bb0 = (wid & 3) * 16;           // warp batch-rows
    const int hh0 = (wid >> 2) * 32;          // warp hidden-cols (within 64)

    // stage step-invariant W slice (hi+lo): 64 rows x 128 k (16 uint4/row)
#pragma unroll
    for (int i = 0; i < 4; i++) {
        int q = tid + i * 256;                // 0..1023
        int row = q >> 4, c16 = q & 15;
        size_t wo = (size_t)(h0c + row) * kH + k0 + c16 * 8;
        *(uint4*)(pWh + row * RS + c16 * 16) = *(const uint4*)(Whi + wo);
        *(uint4*)(pWl + row * RS + c16 * 16) = *(const uint4*)(Wlo + wo);
    }

    const uint32_t aOffH = smem_u32(pHh) + (bb0 + (lane & 15)) * RS + (lane >> 4) * 16;
    const uint32_t aOffL = smem_u32(pHl) + (bb0 + (lane & 15)) * RS + (lane >> 4) * 16;
    const int brow = hh0 + (lane & 7) + ((lane >> 4) & 1) * 8;
    const uint32_t bOffH = smem_u32(pWh) + brow * RS + ((lane >> 3) & 1) * 16;
    const uint32_t bOffL = smem_u32(pWl) + brow * RS + ((lane >> 3) & 1) * 16;

    const int lin = (cta * 256 + tid) * 2;    // phase-B: 2 elems/thread
    const int g = lane >> 2, tg2 = (lane & 3) * 2;
    float* pp = g_s.part + (size_t)kc * kBH;

    for (int t = 0; t < kT; t++) {
        const bf16* sh = t ? (Yhi + (size_t)(t - 1) * ystride) : initHi;
        const bf16* sl = t ? (Ylo + (size_t)(t - 1) * ystride) : initLo;
        // stage h tile [64 b][128 k] hi+lo; __ldcg (cross-SM within launch)
#pragma unroll
        for (int i = 0; i < 4; i++) {
            int q = tid + i * 256;
            int row = q >> 4, c16 = q & 15;
            size_t ho = (size_t)row * kH + k0 + c16 * 8;
            uint4 vh = __ldcg((const uint4*)(sh + ho));
            uint4 vl = __ldcg((const uint4*)(sl + ho));
            *(uint4*)(pHh + row * RS + c16 * 16) = vh;
            *(uint4*)(pHl + row * RS + c16 * 16) = vl;
        }
        __syncthreads();

        float acc[4][4];
#pragma unroll
        for (int a = 0; a < 4; a++)
#pragma unroll
            for (int c = 0; c < 4; c++) acc[a][c] = 0.f;

#pragma unroll
        for (int kk = 0; kk < 8; kk++) {
            uint32_t ah[4], al[4], bh0[4], bh1[4], bl0[4], bl1[4];
            LDSM4(ah, aOffH + kk * 32);
            LDSM4(al, aOffL + kk * 32);
            LDSM4(bh0, bOffH + kk * 32);
            LDSM4(bh1, bOffH + 16 * RS + kk * 32);
            LDSM4(bl0, bOffL + kk * 32);
            LDSM4(bl1, bOffL + 16 * RS + kk * 32);
            HMMA(acc[0], ah, bh0+0); HMMA(acc[1], ah, bh0+2);
            HMMA(acc[2], ah, bh1+0); HMMA(acc[3], ah, bh1+2);
            HMMA(acc[0], ah, bl0+0); HMMA(acc[1], ah, bl0+2);
            HMMA(acc[2], ah, bl1+0); HMMA(acc[3], ah, bl1+2);
            HMMA(acc[0], al, bh0+0); HMMA(acc[1], al, bh0+2);
            HMMA(acc[2], al, bh1+0); HMMA(acc[3], al, bh1+2);
        }

        // store partial: part[kc][b][hidden]
        {
            int b  = bb0 + g;
            int hc = h0c + hh0 + tg2;
#pragma unroll
            for (int nt = 0; nt < 4; nt++) {
                *(float2*)(pp + (size_t)b * kH + hc + nt * 8) =
                    make_float2(acc[nt][0], acc[nt][1]);
                *(float2*)(pp + (size_t)(b + 8) * kH + hc + nt * 8) =
                    make_float2(acc[nt][2], acc[nt][3]);
            }
        }

        gridbar();

        // Phase B: reduce 8 partials + X, tanh, publish split h
        {
            float2 s = *(const float2*)(X + (size_t)t * kBH + lin);
#pragma unroll
            for (int j = 0; j < 8; j++) {
                float2 p = __ldcg((const float2*)(g_s.part + (size_t)j * kBH + lin));
                s.x += p.x; s.y += p.y;
            }
            float hx = tanhf(s.x), hy = tanhf(s.y);
            if (Yfp) *(float2*)(Yfp + (size_t)t * kBH + lin) = make_float2(hx, hy);
            bf16 hxh = __float2bfloat16(hx), hyh = __float2bfloat16(hy);
            *(__nv_bfloat162*)(Yhi + (size_t)t * ystride + lin) =
                __halves2bfloat162(hxh, hyh);
            *(__nv_bfloat162*)(Ylo + (size_t)t * ystride + lin) =
                __halves2bfloat162(__float2bfloat16(hx - __bfloat162float(hxh)),
                                   __float2bfloat16(hy - __bfloat162float(hyh)));
            if (t == kT - 1) *(float2*)(hfinal + lin) = make_float2(hx, hy);
        }

        gridbar();
    }
}

// ---------------------------------------------------------------------------
// Launch
// ---------------------------------------------------------------------------
extern "C" void kernel_launch(void* const* d_in, const int* in_sizes, int n_in,
                              void* d_out, int out_size)
{
    const float* input = (const float*)d_in[0];
    const float* h_0   = (const float*)d_in[1];
    const float* W_ih0 = (const float*)d_in[2];
    const float* b_ih0 = (const float*)d_in[3];
    const float* W_hh0 = (const float*)d_in[4];
    const float* b_hh0 = (const float*)d_in[5];
    const float* W_ih1 = (const float*)d_in[6];
    const float* b_ih1 = (const float*)d_in[7];
    const float* W_hh1 = (const float*)d_in[8];
    const float* b_hh1 = (const float*)d_in[9];
    float* out = (float*)d_out;

    Scratch* s = nullptr;
    cudaGetSymbolAddress((void**)&s, g_s);

    const int gemm_smem = 4 * 128 * 144;   // 73728
    const int rnn_smem  = 4 * 64 * 272;    // 69632
    cudaFuncSetAttribute(gemm_mma, cudaFuncAttributeMaxDynamicSharedMemorySize, gemm_smem);
    cudaFuncSetAttribute(rnn_mma,  cudaFuncAttributeMaxDynamicSharedMemorySize, rnn_smem);

    // Split inputs / weights / h0 into bf16 hi+lo; combine biases
    split_pair<<<2048, 256>>>(input, s->Ahi, s->Alo, kTBH / 4);
    split_pair<<<1024, 256>>>(W_ih0, s->Whi[0], s->Wlo[0], kH * kH / 4);
    split_pair<<<1024, 256>>>(W_hh0, s->Whi[1], s->Wlo[1], kH * kH / 4);
    split_pair<<<1024, 256>>>(W_ih1, s->Whi[2], s->Wlo[2], kH * kH / 4);
    split_pair<<<1024, 256>>>(W_hh1, s->Whi[3], s->Wlo[3], kH * kH / 4);
    split_pair<<<128, 256>>>(h_0, s->hinhi, s->hinlo, 2 * kBH / 4);
    bias2<<<4, 256>>>(b_ih0, b_hh0, b_ih1, b_hh1, s->bias[0], s->bias[1]);

    dim3 ggrid(kH / 128, kTB / 128);       // (8, 256)

    // X0 = input @ W_ih0^T + b_ih0 + b_hh0
    gemm_mma<<<ggrid, 256, gemm_smem>>>(s->Ahi, s->Alo, s->Whi[0], s->Wlo[0],
                                        s->bias[0], s->X);
    // Layer-0 recurrence -> Yhi/Ylo history; final h0 -> out[T*B*H ..]
    rnn_mma<<<RNN_NBLK, 256, rnn_smem>>>(s->Whi[1], s->Wlo[1], s->hinhi, s->hinlo,
                                         s->Yhi, s->Ylo, kBH,
                                         s->X, nullptr, out + (size_t)kTBH);
    // X1 = H0all @ W_ih1^T + b_ih1 + b_hh1  (consumes bf16 split directly)
    gemm_mma<<<ggrid, 256, gemm_smem>>>(s->Yhi, s->Ylo, s->Whi[2], s->Wlo[2],
                                        s->bias[1], s->X);
    // Layer-1 recurrence -> outputs; final h1 -> out[T*B*H + B*H ..]
    rnn_mma<<<RNN_NBLK, 256, rnn_smem>>>(s->Whi[3], s->Wlo[3],
                                         s->hinhi + kBH, s->hinlo + kBH,
                                         s->h1hi, s->h1lo, 0,
                                         s->X, out, out + (size_t)kTBH + kBH);
}

// round 6
// speedup vs baseline: 2.3465x; 1.4250x over previous
#include <cuda_runtime.h>
#include <cuda_bf16.h>
#include <math.h>
#include <stdint.h>

#define kT   512
#define kB   64
#define kH   1024
#define kBH  65536
#define kTB  32768
#define kTBH 33554432
#define RNN_NBLK 128

typedef __nv_bfloat16 bf16;

// ---------------------------------------------------------------------------
// Scratch (device globals; allocations forbidden)
// ---------------------------------------------------------------------------
struct __align__(16) Scratch {
    float X[kTBH];                        // X0 = input @ W_ih0^T + biases
    bf16  Ahi[kTBH], Alo[kTBH];           // split input
    bf16  Whi[4][kH * kH];                // split weights: ih0, hh0, ih1, hh1
    bf16  Wlo[4][kH * kH];
    float bias[2][kH];
    bf16  hinhi[2 * kBH], hinlo[2 * kBH]; // split initial h (layer0, layer1)
    bf16  h0hi[kBH], h0lo[kBH];           // running h0 (bf16 split)
    bf16  h1hi[kBH], h1lo[kBH];           // running h1
    float part[2][8 * (size_t)kBH];       // per-layer k-split partials
};
__device__ Scratch g_s;
__device__ unsigned g_gen = 0, g_cnt = 0;

// ---------------------------------------------------------------------------
// Warp MMA primitives (baseline ISA: HMMA + ldmatrix; no sm_103a features)
// ---------------------------------------------------------------------------
__device__ __forceinline__ uint32_t smem_u32(const void* p) {
    uint32_t r;
    asm("{ .reg .u64 t; cvta.to.shared.u64 t, %1; cvt.u32.u64 %0, t; }" : "=r"(r) : "l"(p));
    return r;
}
#define LDSM4(r, addr)                                                        \
    asm volatile("ldmatrix.sync.aligned.m8n8.x4.shared.b16 {%0,%1,%2,%3}, [%4];" \
        : "=r"((r)[0]), "=r"((r)[1]), "=r"((r)[2]), "=r"((r)[3]) : "r"(addr))
#define HMMA(d, a, b)                                                         \
    asm volatile("mma.sync.aligned.m16n8k16.row.col.f32.bf16.bf16.f32 "       \
        "{%0,%1,%2,%3}, {%4,%5,%6,%7}, {%8,%9}, {%0,%1,%2,%3};"               \
        : "+f"((d)[0]), "+f"((d)[1]), "+f"((d)[2]), "+f"((d)[3])              \
        : "r"((a)[0]), "r"((a)[1]), "r"((a)[2]), "r"((a)[3]),                 \
          "r"((b)[0]), "r"((b)[1]))

// ---------------------------------------------------------------------------
// Grid-wide barrier
// ---------------------------------------------------------------------------
__device__ __forceinline__ void gridbar() {
    __threadfence();
    __syncthreads();
    if (threadIdx.x == 0) {
        volatile unsigned* vg = &g_gen;
        unsigned target = *vg + 1u;
        if (atomicAdd(&g_cnt, 1u) == (unsigned)(RNN_NBLK - 1)) {
            g_cnt = 0u;
            __threadfence();
            *vg = target;
        } else {
            while (*vg != target) { __nanosleep(20); }
        }
    }
    __syncthreads();
}

// ---------------------------------------------------------------------------
// fp32 -> bf16 hi/lo split  |  bias combine
// ---------------------------------------------------------------------------
__global__ void split_pair(const float* __restrict__ s, bf16* __restrict__ hi,
                           bf16* __restrict__ lo, int n4) {
    int stride = gridDim.x * blockDim.x;
    for (int i = blockIdx.x * blockDim.x + threadIdx.x; i < n4; i += stride) {
        float4 v = ((const float4*)s)[i];
        bf16 h0 = __float2bfloat16(v.x), h1 = __float2bfloat16(v.y);
        bf16 h2 = __float2bfloat16(v.z), h3 = __float2bfloat16(v.w);
        ((__nv_bfloat162*)hi)[i * 2 + 0] = __halves2bfloat162(h0, h1);
        ((__nv_bfloat162*)hi)[i * 2 + 1] = __halves2bfloat162(h2, h3);
        ((__nv_bfloat162*)lo)[i * 2 + 0] = __halves2bfloat162(
            __float2bfloat16(v.x - __bfloat162float(h0)),
            __float2bfloat16(v.y - __bfloat162float(h1)));
        ((__nv_bfloat162*)lo)[i * 2 + 1] = __halves2bfloat162(
            __float2bfloat16(v.z - __bfloat162float(h2)),
            __float2bfloat16(v.w - __bfloat162float(h3)));
    }
}
__global__ void bias2(const float* a, const float* b, const float* c,
                      const float* d, float* o0, float* o1) {
    int i = blockIdx.x * 256 + threadIdx.x;
    if (i < kH) { o0[i] = a[i] + b[i]; o1[i] = c[i] + d[i]; }
}

// ---------------------------------------------------------------------------
// Big HMMA GEMM for X0 (identical to proven R4 kernel)
// ---------------------------------------------------------------------------
__global__ void __launch_bounds__(256) gemm_mma(
    const bf16* __restrict__ Ahi, const bf16* __restrict__ Alo,
    const bf16* __restrict__ Whi, const bf16* __restrict__ Wlo,
    const float* __restrict__ bias, float* __restrict__ C)
{
    extern __shared__ char sm[];
    enum { RS = 144, BUF = 128 * 144 };
    char* pAh = sm;            char* pAl = sm + BUF;
    char* pWh = sm + 2 * BUF;  char* pWl = sm + 3 * BUF;

    const int tid = threadIdx.x, lane = tid & 31, wid = tid >> 5;
    const int n0 = blockIdx.x * 128, m0 = blockIdx.y * 128;
    const int wm = (wid >> 1) * 32, wn = (wid & 1) * 64;

    const uint32_t aOffH = smem_u32(pAh) + (wm + (lane & 15)) * RS + (lane >> 4) * 16;
    const uint32_t aOffL = smem_u32(pAl) + (wm + (lane & 15)) * RS + (lane >> 4) * 16;
    const int brow = wn + (lane & 7) + ((lane >> 4) & 1) * 8;
    const uint32_t bOffH = smem_u32(pWh) + brow * RS + ((lane >> 3) & 1) * 16;
    const uint32_t bOffL = smem_u32(pWl) + brow * RS + ((lane >> 3) & 1) * 16;

    float acc[2][8][4];
#pragma unroll
    for (int a = 0; a < 2; a++)
#pragma unroll
        for (int b = 0; b < 8; b++)
#pragma unroll
            for (int c = 0; c < 4; c++) acc[a][b][c] = 0.f;

    for (int k0 = 0; k0 < kH; k0 += 64) {
        __syncthreads();
#pragma unroll
        for (int i = 0; i < 4; i++) {
            int q = tid + i * 256;
            int row = q >> 3, c16 = q & 7;
            size_t ao = (size_t)(m0 + row) * kH + k0 + c16 * 8;
            size_t wo = (size_t)(n0 + row) * kH + k0 + c16 * 8;
            *(uint4*)(pAh + row * RS + c16 * 16) = *(const uint4*)(Ahi + ao);
            *(uint4*)(pAl + row * RS + c16 * 16) = *(const uint4*)(Alo + ao);
            *(uint4*)(pWh + row * RS + c16 * 16) = *(const uint4*)(Whi + wo);
            *(uint4*)(pWl + row * RS + c16 * 16) = *(const uint4*)(Wlo + wo);
        }
        __syncthreads();
#pragma unroll
        for (int kk = 0; kk < 4; kk++) {
            uint32_t ah0[4], ah1[4], al0[4], al1[4];
            LDSM4(ah0, aOffH + kk * 32);
            LDSM4(ah1, aOffH + 16 * RS + kk * 32);
            LDSM4(al0, aOffL + kk * 32);
            LDSM4(al1, aOffL + 16 * RS + kk * 32);
#pragma unroll
            for (int np = 0; np < 4; np++) {
                uint32_t bh[4], bl[4];
                LDSM4(bh, bOffH + np * 16 * RS + kk * 32);
                LDSM4(bl, bOffL + np * 16 * RS + kk * 32);
                HMMA(acc[0][np*2+0], ah0, bh+0); HMMA(acc[0][np*2+1], ah0, bh+2);
                HMMA(acc[1][np*2+0], ah1, bh+0); HMMA(acc[1][np*2+1], ah1, bh+2);
                HMMA(acc[0][np*2+0], ah0, bl+0); HMMA(acc[0][np*2+1], ah0, bl+2);
                HMMA(acc[1][np*2+0], ah1, bl+0); HMMA(acc[1][np*2+1], ah1, bl+2);
                HMMA(acc[0][np*2+0], al0, bh+0); HMMA(acc[0][np*2+1], al0, bh+2);
                HMMA(acc[1][np*2+0], al1, bh+0); HMMA(acc[1][np*2+1], al1, bh+2);
            }
        }
    }
    const int g = lane >> 2, tg2 = (lane & 3) * 2;
#pragma unroll
    for (int mf = 0; mf < 2; mf++)
#pragma unroll
        for (int nt = 0; nt < 8; nt++) {
            int m = m0 + wm + mf * 16 + g;
            int n = n0 + wn + nt * 8 + tg2;
            float b0 = bias[n], b1 = bias[n + 1];
            *(float2*)(C + (size_t)m * kH + n) =
                make_float2(acc[mf][nt][0] + b0, acc[mf][nt][1] + b1);
            *(float2*)(C + (size_t)(m + 8) * kH + n) =
                make_float2(acc[mf][nt][2] + b0, acc[mf][nt][3] + b1);
        }
}

// ---------------------------------------------------------------------------
// Fused 2-layer wavefront recurrence. 128 CTAs: cta<64 -> layer0, else layer1.
// Per layer: 8 hidden-tiles(128) x 8 k-chunks(128). Tick s (0..512):
//   layer0 (s<512):  h0_s = tanh(X0[s] + h0_{s-1} @ Whh0^T)
//   layer1 (s>=1):   h1_{s-1} = tanh(b1 + h0_{s-1} @ Wih1^T + h1_{s-2} @ Whh1^T)
// Phase A (partial MMA) -> gridbar -> Phase B (reduce+tanh+publish) -> gridbar.
// ---------------------------------------------------------------------------
#define RRS 272                     // smem row stride bytes (128 bf16 + 8 pad)
#define WBUF (128 * RRS)            // 34816: one W slice buffer [128 rows]
#define HBUF (64 * RRS)             // 17408: one h tile buffer [64 rows]
// layout: W1h 0 | W1l 1*W | W2h 2*W | W2l 3*W | HAh 4*W | HAl 4W+H | HBh 4W+2H | HBl 4W+3H
#define RNN_SMEM (4 * WBUF + 4 * HBUF)   // 208896

__device__ __forceinline__ void mma_contrib(
    uint32_t aH, uint32_t aL, uint32_t bH, uint32_t bL, float acc[8][4])
{
#pragma unroll
    for (int kk = 0; kk < 8; kk++) {
        uint32_t ah[4], al[4];
        LDSM4(ah, aH + kk * 32);
        LDSM4(al, aL + kk * 32);
#pragma unroll
        for (int np = 0; np < 4; np++) {
            uint32_t bh[4], bl[4];
            LDSM4(bh, bH + np * 16 * RRS + kk * 32);
            LDSM4(bl, bL + np * 16 * RRS + kk * 32);
            HMMA(acc[np*2+0], ah, bh+0); HMMA(acc[np*2+1], ah, bh+2);
            HMMA(acc[np*2+0], ah, bl+0); HMMA(acc[np*2+1], ah, bl+2);
            HMMA(acc[np*2+0], al, bh+0); HMMA(acc[np*2+1], al, bh+2);
        }
    }
}

__device__ __forceinline__ void stage_h(char* dstH, char* dstL,
    const bf16* __restrict__ srcH, const bf16* __restrict__ srcL,
    int k0, int tid)
{
#pragma unroll
    for (int i = 0; i < 4; i++) {
        int q = tid + i * 256;                 // 0..1023
        int row = q >> 4, c16 = q & 15;
        size_t o = (size_t)row * kH + k0 + c16 * 8;
        uint4 vh = __ldcg((const uint4*)(srcH + o));
        uint4 vl = __ldcg((const uint4*)(srcL + o));
        *(uint4*)(dstH + row * RRS + c16 * 16) = vh;
        *(uint4*)(dstL + row * RRS + c16 * 16) = vl;
    }
}

__global__ void __launch_bounds__(256) rnn_fused(
    const float* __restrict__ out_y,    // [T,B,H] fp32 outputs (h1)
    float* __restrict__ hfin0, float* __restrict__ hfin1)
{
    extern __shared__ char sm[];
    const int tid = threadIdx.x, lane = tid & 31, wid = tid >> 5;
    const int cta = blockIdx.x;
    const int layer = cta >> 6;              // 0 or 1
    const int il = cta & 63;                 // index within layer
    const int mt = il >> 3, kc = il & 7;
    const int h0c = mt * 128;                // hidden-column base of this tile
    const int k0 = kc * 128;
    const int bb0 = (wid & 3) * 16;          // warp batch rows
    const int hh0 = (wid >> 2) * 64;         // warp hidden cols within 128

    char* pW1h = sm;             char* pW1l = sm + WBUF;
    char* pW2h = sm + 2 * WBUF;  char* pW2l = sm + 3 * WBUF;
    char* pHAh = sm + 4 * WBUF;            char* pHAl = pHAh + HBUF;
    char* pHBh = sm + 4 * WBUF + 2 * HBUF; char* pHBl = pHBh + HBUF;

    // ---- stage step-invariant W slices ----
    // layer0: W1 = Whh0.  layer1: W1 = Wih1, W2 = Whh1.
    {
        const bf16* w1h = (layer == 0 ? g_s.Whi[1] : g_s.Whi[2]);
        const bf16* w1l = (layer == 0 ? g_s.Wlo[1] : g_s.Wlo[2]);
#pragma unroll
        for (int i = 0; i < 8; i++) {
            int q = tid + i * 256;             // 0..2047
            int row = q >> 4, c16 = q & 15;
            size_t o = (size_t)(h0c + row) * kH + k0 + c16 * 8;
            *(uint4*)(pW1h + row * RRS + c16 * 16) = *(const uint4*)(w1h + o);
            *(uint4*)(pW1l + row * RRS + c16 * 16) = *(const uint4*)(w1l + o);
        }
        if (layer == 1) {
#pragma unroll
            for (int i = 0; i < 8; i++) {
                int q = tid + i * 256;
                int row = q >> 4, c16 = q & 15;
                size_t o = (size_t)(h0c + row) * kH + k0 + c16 * 8;
                *(uint4*)(pW2h + row * RRS + c16 * 16) = *(const uint4*)(g_s.Whi[3] + o);
                *(uint4*)(pW2l + row * RRS + c16 * 16) = *(const uint4*)(g_s.Wlo[3] + o);
            }
        }
    }

    // ldmatrix offsets
    const uint32_t aAH = smem_u32(pHAh) + (bb0 + (lane & 15)) * RRS + (lane >> 4) * 16;
    const uint32_t aAL = smem_u32(pHAl) + (bb0 + (lane & 15)) * RRS + (lane >> 4) * 16;
    const uint32_t aBH = smem_u32(pHBh) + (bb0 + (lane & 15)) * RRS + (lane >> 4) * 16;
    const uint32_t aBL = smem_u32(pHBl) + (bb0 + (lane & 15)) * RRS + (lane >> 4) * 16;
    const int brow = hh0 + (lane & 7) + ((lane >> 4) & 1) * 8;
    const uint32_t b1H = smem_u32(pW1h) + brow * RRS + ((lane >> 3) & 1) * 16;
    const uint32_t b1L = smem_u32(pW1l) + brow * RRS + ((lane >> 3) & 1) * 16;
    const uint32_t b2H = smem_u32(pW2h) + brow * RRS + ((lane >> 3) & 1) * 16;
    const uint32_t b2L = smem_u32(pW2l) + brow * RRS + ((lane >> 3) & 1) * 16;

    const int g = lane >> 2, tg2 = (lane & 3) * 2;
    float* ppart = g_s.part[layer] + (size_t)kc * kBH;
    const int lin = (il * 256 + tid) * 4;      // phase-B: 4 elems per thread
    const int hcol = lin & (kH - 1);           // hidden index of the 4 elems

    for (int s = 0; s <= kT; s++) {
        const bool act = (layer == 0) ? (s < kT) : (s >= 1);

        // ---- Phase A ----
        if (act) {
            if (layer == 0) {
                stage_h(pHAh, pHAl,
                        s == 0 ? g_s.hinhi : g_s.h0hi,
                        s == 0 ? g_s.hinlo : g_s.h0lo, k0, tid);
            } else {
                stage_h(pHAh, pHAl, g_s.h0hi, g_s.h0lo, k0, tid);   // h0_{s-1}
                stage_h(pHBh, pHBl,
                        s == 1 ? (g_s.hinhi + kBH) : g_s.h1hi,
                        s == 1 ? (g_s.hinlo + kBH) : g_s.h1lo, k0, tid); // h1_{s-2}
            }
            __syncthreads();

            float acc[8][4];
#pragma unroll
            for (int a = 0; a < 8; a++)
#pragma unroll
                for (int c = 0; c < 4; c++) acc[a][c] = 0.f;

            mma_contrib(aAH, aAL, b1H, b1L, acc);          // hh0 / ih1
            if (layer == 1)
                mma_contrib(aBH, aBL, b2H, b2L, acc);      // hh1

            // store partial: part[layer][kc][b][hidden]
            const int b = bb0 + g;
            const int hc = h0c + hh0 + tg2;
#pragma unroll
            for (int nt = 0; nt < 8; nt++) {
                *(float2*)(ppart + (size_t)b * kH + hc + nt * 8) =
                    make_float2(acc[nt][0], acc[nt][1]);
                *(float2*)(ppart + (size_t)(b + 8) * kH + hc + nt * 8) =
                    make_float2(acc[nt][2], acc[nt][3]);
            }
            __syncthreads();   // protect HA/HB smem until all warps done (next stage overwrite)
        }

        gridbar();

        // ---- Phase B ----
        if (act) {
            float4 sum;
            if (layer == 0) {
                sum = *(const float4*)(g_s.X + (size_t)s * kBH + lin);
            } else {
                sum = *(const float4*)(g_s.bias[1] + hcol);
            }
            const float* pl = g_s.part[layer];
#pragma unroll
            for (int j = 0; j < 8; j++) {
                float4 p = __ldcg((const float4*)(pl + (size_t)j * kBH + lin));
                sum.x += p.x; sum.y += p.y; sum.z += p.z; sum.w += p.w;
            }
            float4 h4 = make_float4(tanhf(sum.x), tanhf(sum.y),
                                    tanhf(sum.z), tanhf(sum.w));

            bf16 q0 = __float2bfloat16(h4.x), q1 = __float2bfloat16(h4.y);
            bf16 q2 = __float2bfloat16(h4.z), q3 = __float2bfloat16(h4.w);
            bf16* dh = (layer == 0) ? g_s.h0hi : g_s.h1hi;
            bf16* dl = (layer == 0) ? g_s.h0lo : g_s.h1lo;
            ((__nv_bfloat162*)(dh + lin))[0] = __halves2bfloat162(q0, q1);
            ((__nv_bfloat162*)(dh + lin))[1] = __halves2bfloat162(q2, q3);
            ((__nv_bfloat162*)(dl + lin))[0] = __halves2bfloat162(
                __float2bfloat16(h4.x - __bfloat162float(q0)),
                __float2bfloat16(h4.y - __bfloat162float(q1)));
            ((__nv_bfloat162*)(dl + lin))[1] = __halves2bfloat162(
                __float2bfloat16(h4.z - __bfloat162float(q2)),
                __float2bfloat16(h4.w - __bfloat162float(q3)));

            if (layer == 1)
                *(float4*)((float*)out_y + (size_t)(s - 1) * kBH + lin) = h4;
            if (layer == 0 && s == kT - 1) *(float4*)(hfin0 + lin) = h4;
            if (layer == 1 && s == kT)     *(float4*)(hfin1 + lin) = h4;
        }

        gridbar();
    }
}

// ---------------------------------------------------------------------------
// Launch
// ---------------------------------------------------------------------------
extern "C" void kernel_launch(void* const* d_in, const int* in_sizes, int n_in,
                              void* d_out, int out_size)
{
    const float* input = (const float*)d_in[0];
    const float* h_0   = (const float*)d_in[1];
    const float* W_ih0 = (const float*)d_in[2];
    const float* b_ih0 = (const float*)d_in[3];
    const float* W_hh0 = (const float*)d_in[4];
    const float* b_hh0 = (const float*)d_in[5];
    const float* W_ih1 = (const float*)d_in[6];
    const float* b_ih1 = (const float*)d_in[7];
    const float* W_hh1 = (const float*)d_in[8];
    const float* b_hh1 = (const float*)d_in[9];
    float* out = (float*)d_out;

    Scratch* s = nullptr;
    cudaGetSymbolAddress((void**)&s, g_s);

    const int gemm_smem = 4 * 128 * 144;   // 73728
    cudaFuncSetAttribute(gemm_mma, cudaFuncAttributeMaxDynamicSharedMemorySize, gemm_smem);
    cudaFuncSetAttribute(rnn_fused, cudaFuncAttributeMaxDynamicSharedMemorySize, RNN_SMEM);

    // Split inputs / weights / h0; combine biases
    split_pair<<<2048, 256>>>(input, s->Ahi, s->Alo, kTBH / 4);
    split_pair<<<1024, 256>>>(W_ih0, s->Whi[0], s->Wlo[0], kH * kH / 4);
    split_pair<<<1024, 256>>>(W_hh0, s->Whi[1], s->Wlo[1], kH * kH / 4);
    split_pair<<<1024, 256>>>(W_ih1, s->Whi[2], s->Wlo[2], kH * kH / 4);
    split_pair<<<1024, 256>>>(W_hh1, s->Whi[3], s->Wlo[3], kH * kH / 4);
    split_pair<<<128, 256>>>(h_0, s->hinhi, s->hinlo, 2 * kBH / 4);
    bias2<<<4, 256>>>(b_ih0, b_hh0, b_ih1, b_hh1, s->bias[0], s->bias[1]);

    // X0 = input @ W_ih0^T + b_ih0 + b_hh0
    dim3 ggrid(kH / 128, kTB / 128);
    gemm_mma<<<ggrid, 256, gemm_smem>>>(s->Ahi, s->Alo, s->Whi[0], s->Wlo[0],
                                        s->bias[0], s->X);

    // Fused wavefront recurrence: outputs + final states
    rnn_fused<<<RNN_NBLK, 256, RNN_SMEM>>>(out, out + (size_t)kTBH,
                                           out + (size_t)kTBH + kBH);
}

// round 9
// speedup vs baseline: 2.6077x; 1.1113x over previous
#include <cuda_runtime.h>
#include <cuda_bf16.h>
#include <math.h>
#include <stdint.h>

#define kT   512
#define kB   64
#define kH   1024
#define kBH  65536
#define kTB  32768
#define kTBH 33554432
#define RNN_NBLK 128

typedef __nv_bfloat16 bf16;

// ---------------------------------------------------------------------------
// Scratch (device globals; allocations forbidden)
// ---------------------------------------------------------------------------
struct __align__(16) Scratch {
    float X[kTBH];                        // X0 = input @ W_ih0^T + biases
    bf16  Ahi[kTBH], Alo[kTBH];           // split input
    bf16  Whi[4][kH * kH];                // split weights: ih0, hh0, ih1, hh1
    bf16  Wlo[4][kH * kH];
    float bias[2][kH];
    bf16  hinhi[2 * kBH], hinlo[2 * kBH]; // split initial h (layer0, layer1)
};
__device__ Scratch g_s;

// write-once hidden-state histories (bf16 split)
__device__ bf16 g_h0hi[kTBH], g_h0lo[kTBH];
__device__ bf16 g_h1hi[kTBH], g_h1lo[kTBH];

// k-split partials: [layer][slot=t&1][mt][kc][64*128]
__device__ float g_part[2][2][8][8][64 * 128];

// dataflow flags (monotonic counters, zeroed per launch)
__device__ int g_hf[2][kT][8];            // h[layer][t][tile] published count
__device__ int g_pf[2][kT][8];            // partial[layer][t][tile] ready count

// ---------------------------------------------------------------------------
// Warp MMA primitives (baseline ISA: HMMA + ldmatrix; no sm_103a features)
// ---------------------------------------------------------------------------
__device__ __forceinline__ uint32_t smem_u32(const void* p) {
    uint32_t r;
    asm("{ .reg .u64 t; cvta.to.shared.u64 t, %1; cvt.u32.u64 %0, t; }" : "=r"(r) : "l"(p));
    return r;
}
#define LDSM4(r, addr)                                                        \
    asm volatile("ldmatrix.sync.aligned.m8n8.x4.shared.b16 {%0,%1,%2,%3}, [%4];" \
        : "=r"((r)[0]), "=r"((r)[1]), "=r"((r)[2]), "=r"((r)[3]) : "r"(addr))
#define HMMA(d, a, b)                                                         \
    asm volatile("mma.sync.aligned.m16n8k16.row.col.f32.bf16.bf16.f32 "       \
        "{%0,%1,%2,%3}, {%4,%5,%6,%7}, {%8,%9}, {%0,%1,%2,%3};"               \
        : "+f"((d)[0]), "+f"((d)[1]), "+f"((d)[2]), "+f"((d)[3])              \
        : "r"((a)[0]), "r"((a)[1]), "r"((a)[2]), "r"((a)[3]),                 \
          "r"((b)[0]), "r"((b)[1]))

// flag ops: producer = (syncthreads); tid0: threadfence + atomicAdd.
// consumer = tid0 spins on acquire-load; then syncthreads.
__device__ __forceinline__ void spin_ge8(const int* f) {
    while (true) {
        int v;
        asm volatile("ld.acquire.gpu.global.s32 %0, [%1];" : "=r"(v) : "l"(f));
        if (v >= 8) break;
        __nanosleep(20);
    }
}

// ---------------------------------------------------------------------------
// fp32 -> bf16 hi/lo split  |  bias combine  |  flag reset
// ---------------------------------------------------------------------------
__global__ void split_pair(const float* __restrict__ s, bf16* __restrict__ hi,
                           bf16* __restrict__ lo, int n4) {
    int stride = gridDim.x * blockDim.x;
    for (int i = blockIdx.x * blockDim.x + threadIdx.x; i < n4; i += stride) {
        float4 v = ((const float4*)s)[i];
        bf16 h0 = __float2bfloat16(v.x), h1 = __float2bfloat16(v.y);
        bf16 h2 = __float2bfloat16(v.z), h3 = __float2bfloat16(v.w);
        ((__nv_bfloat162*)hi)[i * 2 + 0] = __halves2bfloat162(h0, h1);
        ((__nv_bfloat162*)hi)[i * 2 + 1] = __halves2bfloat162(h2, h3);
        ((__nv_bfloat162*)lo)[i * 2 + 0] = __halves2bfloat162(
            __float2bfloat16(v.x - __bfloat162float(h0)),
            __float2bfloat16(v.y - __bfloat162float(h1)));
        ((__nv_bfloat162*)lo)[i * 2 + 1] = __halves2bfloat162(
            __float2bfloat16(v.z - __bfloat162float(h2)),
            __float2bfloat16(v.w - __bfloat162float(h3)));
    }
}
__global__ void bias2(const float* a, const float* b, const float* c,
                      const float* d, float* o0, float* o1) {
    int i = blockIdx.x * 256 + threadIdx.x;
    if (i < kH) { o0[i] = a[i] + b[i]; o1[i] = c[i] + d[i]; }
}
__global__ void zero_flags() {
    int i = blockIdx.x * 256 + threadIdx.x;
    const int n = 2 * kT * 8;
    if (i < n) { ((int*)g_hf)[i] = 0; ((int*)g_pf)[i] = 0; }
}

// ---------------------------------------------------------------------------
// Big HMMA GEMM for X0 (proven R4 kernel, unchanged)
// ---------------------------------------------------------------------------
__global__ void __launch_bounds__(256) gemm_mma(
    const bf16* __restrict__ Ahi, const bf16* __restrict__ Alo,
    const bf16* __restrict__ Whi, const bf16* __restrict__ Wlo,
    const float* __restrict__ bias, float* __restrict__ C)
{
    extern __shared__ char sm[];
    enum { RS = 144, BUF = 128 * 144 };
    char* pAh = sm;            char* pAl = sm + BUF;
    char* pWh = sm + 2 * BUF;  char* pWl = sm + 3 * BUF;

    const int tid = threadIdx.x, lane = tid & 31, wid = tid >> 5;
    const int n0 = blockIdx.x * 128, m0 = blockIdx.y * 128;
    const int wm = (wid >> 1) * 32, wn = (wid & 1) * 64;

    const uint32_t aOffH = smem_u32(pAh) + (wm + (lane & 15)) * RS + (lane >> 4) * 16;
    const uint32_t aOffL = smem_u32(pAl) + (wm + (lane & 15)) * RS + (lane >> 4) * 16;
    const int brow = wn + (lane & 7) + ((lane >> 4) & 1) * 8;
    const uint32_t bOffH = smem_u32(pWh) + brow * RS + ((lane >> 3) & 1) * 16;
    const uint32_t bOffL = smem_u32(pWl) + brow * RS + ((lane >> 3) & 1) * 16;

    float acc[2][8][4];
#pragma unroll
    for (int a = 0; a < 2; a++)
#pragma unroll
        for (int b = 0; b < 8; b++)
#pragma unroll
            for (int c = 0; c < 4; c++) acc[a][b][c] = 0.f;

    for (int k0 = 0; k0 < kH; k0 += 64) {
        __syncthreads();
#pragma unroll
        for (int i = 0; i < 4; i++) {
            int q = tid + i * 256;
            int row = q >> 3, c16 = q & 7;
            size_t ao = (size_t)(m0 + row) * kH + k0 + c16 * 8;
            size_t wo = (size_t)(n0 + row) * kH + k0 + c16 * 8;
            *(uint4*)(pAh + row * RS + c16 * 16) = *(const uint4*)(Ahi + ao);
            *(uint4*)(pAl + row * RS + c16 * 16) = *(const uint4*)(Alo + ao);
            *(uint4*)(pWh + row * RS + c16 * 16) = *(const uint4*)(Whi + wo);
            *(uint4*)(pWl + row * RS + c16 * 16) = *(const uint4*)(Wlo + wo);
        }
        __syncthreads();
#pragma unroll
        for (int kk = 0; kk < 4; kk++) {
            uint32_t ah0[4], ah1[4], al0[4], al1[4];
            LDSM4(ah0, aOffH + kk * 32);
            LDSM4(ah1, aOffH + 16 * RS + kk * 32);
            LDSM4(al0, aOffL + kk * 32);
            LDSM4(al1, aOffL + 16 * RS + kk * 32);
#pragma unroll
            for (int np = 0; np < 4; np++) {
                uint32_t bh[4], bl[4];
                LDSM4(bh, bOffH + np * 16 * RS + kk * 32);
                LDSM4(bl, bOffL + np * 16 * RS + kk * 32);
                HMMA(acc[0][np*2+0], ah0, bh+0); HMMA(acc[0][np*2+1], ah0, bh+2);
                HMMA(acc[1][np*2+0], ah1, bh+0); HMMA(acc[1][np*2+1], ah1, bh+2);
                HMMA(acc[0][np*2+0], ah0, bl+0); HMMA(acc[0][np*2+1], ah0, bl+2);
                HMMA(acc[1][np*2+0], ah1, bl+0); HMMA(acc[1][np*2+1], ah1, bl+2);
                HMMA(acc[0][np*2+0], al0, bh+0); HMMA(acc[0][np*2+1], al0, bh+2);
                HMMA(acc[1][np*2+0], al1, bh+0); HMMA(acc[1][np*2+1], al1, bh+2);
            }
        }
    }
    const int g = lane >> 2, tg2 = (lane & 3) * 2;
#pragma unroll
    for (int mf = 0; mf < 2; mf++)
#pragma unroll
        for (int nt = 0; nt < 8; nt++) {
            int m = m0 + wm + mf * 16 + g;
            int n = n0 + wn + nt * 8 + tg2;
            float b0 = bias[n], b1 = bias[n + 1];
            *(float2*)(C + (size_t)m * kH + n) =
                make_float2(acc[mf][nt][0] + b0, acc[mf][nt][1] + b1);
            *(float2*)(C + (size_t)(m + 8) * kH + n) =
                make_float2(acc[mf][nt][2] + b0, acc[mf][nt][3] + b1);
        }
}

// ---------------------------------------------------------------------------
// Fused 2-layer self-timed recurrence (flag dataflow; NO grid barrier).
// 128 CTAs: layer = cta>>6; tile mt = (cta>>3)&7; k-chunk kc = cta&7.
//   layer0 step t: h0[t] = tanh(X0[t] + h0[t-1] @ Whh0^T)
//   layer1 step t: h1[t] = tanh(b1 + h0[t] @ Wih1^T + h1[t-1] @ Whh1^T)
// Per step: wait deps -> stage h -> MMA partial -> global partial + pflag ->
//           wait pflag==8 -> reduce own 16-col slice + tanh -> publish + hflag.
// ---------------------------------------------------------------------------
#define RRS 272
#define WBUF (128 * RRS)
#define HBUF (64 * RRS)
#define RNN_SMEM (4 * WBUF + 4 * HBUF)   // 208896

__device__ __forceinline__ void mma_contrib(
    uint32_t aH, uint32_t aL, uint32_t bH, uint32_t bL, float acc[8][4])
{
#pragma unroll
    for (int kk = 0; kk < 8; kk++) {
        uint32_t ah[4], al[4];
        LDSM4(ah, aH + kk * 32);
        LDSM4(al, aL + kk * 32);
#pragma unroll
        for (int np = 0; np < 4; np++) {
            uint32_t bh[4], bl[4];
            LDSM4(bh, bH + np * 16 * RRS + kk * 32);
            LDSM4(bl, bL + np * 16 * RRS + kk * 32);
            HMMA(acc[np*2+0], ah, bh+0); HMMA(acc[np*2+1], ah, bh+2);
            HMMA(acc[np*2+0], ah, bl+0); HMMA(acc[np*2+1], ah, bl+2);
            HMMA(acc[np*2+0], al, bh+0); HMMA(acc[np*2+1], al, bh+2);
        }
    }
}

__device__ __forceinline__ void stage_h(char* dstH, char* dstL,
    const bf16* __restrict__ srcH, const bf16* __restrict__ srcL,
    int k0, int tid)
{
#pragma unroll
    for (int i = 0; i < 4; i++) {
        int q = tid + i * 256;
        int row = q >> 4, c16 = q & 15;
        size_t o = (size_t)row * kH + k0 + c16 * 8;
        uint4 vh = __ldcg((const uint4*)(srcH + o));
        uint4 vl = __ldcg((const uint4*)(srcL + o));
        *(uint4*)(dstH + row * RRS + c16 * 16) = vh;
        *(uint4*)(dstL + row * RRS + c16 * 16) = vl;
    }
}

__global__ void __launch_bounds__(256) rnn_fused(
    float* __restrict__ out_y, float* __restrict__ hfin0,
    float* __restrict__ hfin1)
{
    extern __shared__ char sm[];
    const int tid = threadIdx.x, lane = tid & 31, wid = tid >> 5;
    const int cta = blockIdx.x;
    const int layer = cta >> 6;
    const int mt = (cta >> 3) & 7;
    const int kc = cta & 7;
    const int h0c = mt * 128;
    const int k0 = kc * 128;
    const int bb0 = (wid & 3) * 16;
    const int hh0 = (wid >> 2) * 64;

    char* pW1h = sm;             char* pW1l = sm + WBUF;
    char* pW2h = sm + 2 * WBUF;  char* pW2l = sm + 3 * WBUF;
    char* pHAh = sm + 4 * WBUF;            char* pHAl = pHAh + HBUF;
    char* pHBh = sm + 4 * WBUF + 2 * HBUF; char* pHBl = pHBh + HBUF;

    // ---- stage step-invariant W slices ----
    {
        const bf16* w1h = (layer == 0 ? g_s.Whi[1] : g_s.Whi[2]);
        const bf16* w1l = (layer == 0 ? g_s.Wlo[1] : g_s.Wlo[2]);
#pragma unroll
        for (int i = 0; i < 8; i++) {
            int q = tid + i * 256;
            int row = q >> 4, c16 = q & 15;
            size_t o = (size_t)(h0c + row) * kH + k0 + c16 * 8;
            *(uint4*)(pW1h + row * RRS + c16 * 16) = *(const uint4*)(w1h + o);
            *(uint4*)(pW1l + row * RRS + c16 * 16) = *(const uint4*)(w1l + o);
        }
        if (layer == 1) {
#pragma unroll
            for (int i = 0; i < 8; i++) {
                int q = tid + i * 256;
                int row = q >> 4, c16 = q & 15;
                size_t o = (size_t)(h0c + row) * kH + k0 + c16 * 8;
                *(uint4*)(pW2h + row * RRS + c16 * 16) = *(const uint4*)(g_s.Whi[3] + o);
                *(uint4*)(pW2l + row * RRS + c16 * 16) = *(const uint4*)(g_s.Wlo[3] + o);
            }
        }
    }

    const uint32_t aAH = smem_u32(pHAh) + (bb0 + (lane & 15)) * RRS + (lane >> 4) * 16;
    const uint32_t aAL = smem_u32(pHAl) + (bb0 + (lane & 15)) * RRS + (lane >> 4) * 16;
    const uint32_t aBH = smem_u32(pHBh) + (bb0 + (lane & 15)) * RRS + (lane >> 4) * 16;
    const uint32_t aBL = smem_u32(pHBl) + (bb0 + (lane & 15)) * RRS + (lane >> 4) * 16;
    const int brow = hh0 + (lane & 7) + ((lane >> 4) & 1) * 8;
    const uint32_t b1H = smem_u32(pW1h) + brow * RRS + ((lane >> 3) & 1) * 16;
    const uint32_t b1L = smem_u32(pW1l) + brow * RRS + ((lane >> 3) & 1) * 16;
    const uint32_t b2H = smem_u32(pW2h) + brow * RRS + ((lane >> 3) & 1) * 16;
    const uint32_t b2L = smem_u32(pW2l) + brow * RRS + ((lane >> 3) & 1) * 16;

    const int g = lane >> 2, tg2 = (lane & 3) * 2;

    // Phase-B ownership: this CTA reduces cols [kc*16, kc*16+16) of tile mt
    const int pb_b  = tid >> 2;                 // batch row 0..63
    const int pb_cg = (tid & 3) * 4;            // 4-col group
    const int pb_cl = kc * 16 + pb_cg;          // col within 128-tile
    const int hcol  = h0c + pb_cl;              // global hidden col
    const int gidx  = pb_b * kH + hcol;

    const bf16* myWriteHi = (layer == 0) ? g_h0hi : g_h1hi;   // for typing only
    (void)myWriteHi;

    for (int t = 0; t < kT; t++) {
        // ---- wait dependencies (tid0 spins; one syncthreads) ----
        if (tid == 0) {
            if (layer == 0) {
                if (t >= 1) spin_ge8(&g_hf[0][t - 1][kc]);
                if (t >= 2) spin_ge8(&g_hf[0][t - 2][mt]);   // partial-slot guard
            } else {
                spin_ge8(&g_hf[0][t][kc]);                   // h0[t]
                if (t >= 1) spin_ge8(&g_hf[1][t - 1][kc]);
                if (t >= 2) spin_ge8(&g_hf[1][t - 2][mt]);   // partial-slot guard
            }
        }
        __syncthreads();   // deps satisfied + previous iter's LDSM reads complete

        // ---- stage h inputs ----
        if (layer == 0) {
            stage_h(pHAh, pHAl,
                    t ? g_h0hi + (size_t)(t - 1) * kBH : g_s.hinhi,
                    t ? g_h0lo + (size_t)(t - 1) * kBH : g_s.hinlo, k0, tid);
        } else {
            stage_h(pHAh, pHAl, g_h0hi + (size_t)t * kBH,
                                g_h0lo + (size_t)t * kBH, k0, tid);
            stage_h(pHBh, pHBl,
                    t ? g_h1hi + (size_t)(t - 1) * kBH : (g_s.hinhi + kBH),
                    t ? g_h1lo + (size_t)(t - 1) * kBH : (g_s.hinlo + kBH), k0, tid);
        }
        __syncthreads();

        // ---- MMA partial ----
        float acc[8][4];
#pragma unroll
        for (int a = 0; a < 8; a++)
#pragma unroll
            for (int c = 0; c < 4; c++) acc[a][c] = 0.f;

        mma_contrib(aAH, aAL, b1H, b1L, acc);
        if (layer == 1)
            mma_contrib(aBH, aBL, b2H, b2L, acc);

        // ---- store partial to global, signal ----
        {
            float* pp = &g_part[layer][t & 1][mt][kc][0];
            const int b = bb0 + g;
#pragma unroll
            for (int nt = 0; nt < 8; nt++) {
                int col = hh0 + nt * 8 + tg2;
                *(float2*)(pp + b * 128 + col) =
                    make_float2(acc[nt][0], acc[nt][1]);
                *(float2*)(pp + (b + 8) * 128 + col) =
                    make_float2(acc[nt][2], acc[nt][3]);
            }
        }
        __syncthreads();
        if (tid == 0) { __threadfence(); atomicAdd(&g_pf[layer][t][mt], 1); }

        // ---- wait all 8 partials of own tile ----
        if (tid == 0) spin_ge8(&g_pf[layer][t][mt]);
        __syncthreads();

        // ---- Phase B: reduce own 16-col slice, tanh, publish ----
        {
            float4 sum;
            if (layer == 0) {
                sum = *(const float4*)(g_s.X + (size_t)t * kBH + gidx);
            } else {
                sum = *(const float4*)(g_s.bias[1] + hcol);
            }
            const float* base = &g_part[layer][t & 1][mt][0][0];
#pragma unroll
            for (int r = 0; r < 8; r++) {
                float4 p = __ldcg((const float4*)(base + r * 8192 + pb_b * 128 + pb_cl));
                sum.x += p.x; sum.y += p.y; sum.z += p.z; sum.w += p.w;
            }
            float4 h4 = make_float4(tanhf(sum.x), tanhf(sum.y),
                                    tanhf(sum.z), tanhf(sum.w));

            bf16 q0 = __float2bfloat16(h4.x), q1 = __float2bfloat16(h4.y);
            bf16 q2 = __float2bfloat16(h4.z), q3 = __float2bfloat16(h4.w);
            bf16* dh = (layer == 0 ? g_h0hi : g_h1hi) + (size_t)t * kBH + gidx;
            bf16* dl = (layer == 0 ? g_h0lo : g_h1lo) + (size_t)t * kBH + gidx;
            ((__nv_bfloat162*)dh)[0] = __halves2bfloat162(q0, q1);
            ((__nv_bfloat162*)dh)[1] = __halves2bfloat162(q2, q3);
            ((__nv_bfloat162*)dl)[0] = __halves2bfloat162(
                __float2bfloat16(h4.x - __bfloat162float(q0)),
                __float2bfloat16(h4.y - __bfloat162float(q1)));
            ((__nv_bfloat162*)dl)[1] = __halves2bfloat162(
                __float2bfloat16(h4.z - __bfloat162float(q2)),
                __float2bfloat16(h4.w - __bfloat162float(q3)));

            if (layer == 1)
                *(float4*)(out_y + (size_t)t * kBH + gidx) = h4;
            if (t == kT - 1) {
                if (layer == 0) *(float4*)(hfin0 + gidx) = h4;
                else            *(float4*)(hfin1 + gidx) = h4;
            }
        }
        __syncthreads();
        if (tid == 0) { __threadfence(); atomicAdd(&g_hf[layer][t][mt], 1); }
    }
}

// ---------------------------------------------------------------------------
// Launch
// ---------------------------------------------------------------------------
extern "C" void kernel_launch(void* const* d_in, const int* in_sizes, int n_in,
                              void* d_out, int out_size)
{
    const float* input = (const float*)d_in[0];
    const float* h_0   = (const float*)d_in[1];
    const float* W_ih0 = (const float*)d_in[2];
    const float* b_ih0 = (const float*)d_in[3];
    const float* W_hh0 = (const float*)d_in[4];
    const float* b_hh0 = (const float*)d_in[5];
    const float* W_ih1 = (const float*)d_in[6];
    const float* b_ih1 = (const float*)d_in[7];
    const float* W_hh1 = (const float*)d_in[8];
    const float* b_hh1 = (const float*)d_in[9];
    float* out = (float*)d_out;

    Scratch* s = nullptr;
    cudaGetSymbolAddress((void**)&s, g_s);

    const int gemm_smem = 4 * 128 * 144;
    cudaFuncSetAttribute(gemm_mma, cudaFuncAttributeMaxDynamicSharedMemorySize, gemm_smem);
    cudaFuncSetAttribute(rnn_fused, cudaFuncAttributeMaxDynamicSharedMemorySize, RNN_SMEM);

    zero_flags<<<32, 256>>>();
    split_pair<<<2048, 256>>>(input, s->Ahi, s->Alo, kTBH / 4);
    split_pair<<<1024, 256>>>(W_ih0, s->Whi[0], s->Wlo[0], kH * kH / 4);
    split_pair<<<1024, 256>>>(W_hh0, s->Whi[1], s->Wlo[1], kH * kH / 4);
    split_pair<<<1024, 256>>>(W_ih1, s->Whi[2], s->Wlo[2], kH * kH / 4);
    split_pair<<<1024, 256>>>(W_hh1, s->Whi[3], s->Wlo[3], kH * kH / 4);
    split_pair<<<128, 256>>>(h_0, s->hinhi, s->hinlo, 2 * kBH / 4);
    bias2<<<4, 256>>>(b_ih0, b_hh0, b_ih1, b_hh1, s->bias[0], s->bias[1]);

    dim3 ggrid(kH / 128, kTB / 128);
    gemm_mma<<<ggrid, 256, gemm_smem>>>(s->Ahi, s->Alo, s->Whi[0], s->Wlo[0],
                                        s->bias[0], s->X);

    rnn_fused<<<RNN_NBLK, 256, RNN_SMEM>>>(out, out + (size_t)kTBH,
                                           out + (size_t)kTBH + kBH);
}